// round 15
// baseline (speedup 1.0000x reference)
#include <cuda_runtime.h>
#include <math.h>
#include <stdint.h>
#include <stddef.h>

// Problem constants
#define BB    64
#define TDEC  1000
#define TMEL  2000
#define MDIM  80
#define PDIM  256
#define EDIM  512
#define HDIM  1024
#define H3    3072
#define OUTC  160
#define ROWS  (TDEC*BB)   // 64000

#define NBLK  148
#define SMEM_FLOATS (4*64*52)           // 4 reduction buffers [64][52]
#define SMEM_BYTES  (SMEM_FLOATS*4)     // 53248 bytes (> gemm staging 48128)

// ---------------- scratch (static device memory; no allocations) ----------------
__device__ float g_di [ROWS*MDIM];
__device__ float g_x1 [ROWS*PDIM];
__device__ float g_x2 [ROWS*PDIM];
__device__ float g_mem[ROWS*EDIM];
__device__ float g_gi1[(size_t)ROWS*H3];
__device__ float g_dm [ROWS*HDIM];
__device__ float g_om [ROWS*OUTC];
__device__ float g_h1 [2*BB*HDIM];
__device__ float g_h2 [2*BB*HDIM];
__device__ float g_h3 [2*BB*HDIM];
__device__ float g_d2 [BB*HDIM];
__device__ float g_r2 [BB*HDIM];
__device__ float g_r3 [BB*HDIM];

__device__ unsigned g_count = 0;
__device__ unsigned g_gen   = 0;

__device__ __forceinline__ float sigf(float x) { return 1.f/(1.f+expf(-x)); }

// ---------------- grid barrier (all NBLK blocks resident) ----------------
__device__ __forceinline__ void gridsync(unsigned &gen) {
    __threadfence();                 // release: make this block's gmem writes visible
    __syncthreads();
    if (threadIdx.x == 0) {
        unsigned target = gen + 1u;
        if (atomicAdd(&g_count, 1u) == NBLK - 1u) {
            g_count = 0;
            __threadfence();
            atomicExch(&g_gen, target);
        } else {
            while (*(volatile unsigned*)&g_gen != target) { }
        }
    }
    __syncthreads();
    gen += 1u;
}

// ---------------- elementwise precompute ----------------
__global__ void build_di(const float* __restrict__ dec, float* __restrict__ di) {
    int i = blockIdx.x*blockDim.x + threadIdx.x;
    if (i >= ROWS*MDIM) return;
    int m = i % MDIM;
    int r = i / MDIM;       // r = t*64 + b
    int b = r % BB;
    int t = r / BB;
    di[i] = (t == 0) ? 0.f : dec[((size_t)b*TMEL + (2*t-1))*MDIM + m];
}

__global__ void pool_mem(const float* __restrict__ mems, float* __restrict__ mem) {
    int i = blockIdx.x*blockDim.x + threadIdx.x;
    if (i >= ROWS*EDIM) return;
    int e = i % EDIM;
    int r = i / EDIM;
    int b = r % BB;
    int t = r / BB;
    size_t base = ((size_t)b*TMEL + 2*t)*EDIM + e;
    mem[i] = 0.5f*(mems[base] + mems[base + EDIM]);
}

// ---------------- big parallel SGEMM (validated in R13) ----------------
__global__ void __launch_bounds__(256) fc128(
    const float* __restrict__ A1, int K1,
    const float* __restrict__ A2, int K2,
    const float* __restrict__ W, int wstride, int woff,
    const float* __restrict__ bias,
    float* __restrict__ C, int N, int doRelu)
{
    __shared__ float As[8][128];
    __shared__ float Ws[8][128];
    const int tid = threadIdx.x;
    const int rowBase = blockIdx.y << 7;
    const int colBase = blockIdx.x << 7;
    const int tx = tid & 15;
    const int ty = tid >> 4;
    const int la_row = tid >> 1;
    const int la_k   = (tid & 1) << 2;
    const int K = K1 + K2;
    float acc[8][8] = {};
    for (int k0 = 0; k0 < K; k0 += 8) {
        {
            int r = rowBase + la_row;
            int k = k0 + la_k;
            const float* src; int kk;
            if (k < K1) { src = A1 + (size_t)r*K1; kk = k; }
            else        { src = A2 + (size_t)r*K2; kk = k - K1; }
            float4 v = *(const float4*)(src + kk);
            As[la_k+0][la_row] = v.x; As[la_k+1][la_row] = v.y;
            As[la_k+2][la_row] = v.z; As[la_k+3][la_row] = v.w;
        }
        {
            int c = colBase + la_row;
            float4 v = make_float4(0.f,0.f,0.f,0.f);
            if (c < N) v = *(const float4*)(W + (size_t)c*wstride + woff + k0 + la_k);
            Ws[la_k+0][la_row] = v.x; Ws[la_k+1][la_row] = v.y;
            Ws[la_k+2][la_row] = v.z; Ws[la_k+3][la_row] = v.w;
        }
        __syncthreads();
#pragma unroll
        for (int kk = 0; kk < 8; kk++) {
            float4 a0 = *(const float4*)&As[kk][ty<<3];
            float4 a1 = *(const float4*)&As[kk][(ty<<3)+4];
            float4 b0 = *(const float4*)&Ws[kk][tx<<3];
            float4 b1 = *(const float4*)&Ws[kk][(tx<<3)+4];
            float a[8]  = {a0.x,a0.y,a0.z,a0.w,a1.x,a1.y,a1.z,a1.w};
            float bw[8] = {b0.x,b0.y,b0.z,b0.w,b1.x,b1.y,b1.z,b1.w};
#pragma unroll
            for (int i = 0; i < 8; i++)
#pragma unroll
                for (int j = 0; j < 8; j++)
                    acc[i][j] = fmaf(a[i], bw[j], acc[i][j]);
        }
        __syncthreads();
    }
#pragma unroll
    for (int i = 0; i < 8; i++) {
        int r = rowBase + (ty<<3) + i;
#pragma unroll
        for (int j = 0; j < 8; j++) {
            int c = colBase + (tx<<3) + j;
            if (c < N) {
                float v = acc[i][j] + bias[c];
                if (doRelu) v = fmaxf(v, 0.f);
                C[(size_t)r*N + c] = v;
            }
        }
    }
}

// ---------------- persistent-kernel phase helpers ----------------
// Stage activation chunk [64 b][64 k] into smem as [b][68] (direct copy, cg loads)
__device__ __forceinline__ void stage_act2(const float* __restrict__ src, int k0,
                                           float* __restrict__ dst) {
    const int tid = threadIdx.x;
    const int b  = tid >> 2;
    const int kq = (tid & 3) << 4;
    const float* s = src + b*HDIM + k0 + kq;
    float* d = dst + b*68 + kq;
#pragma unroll
    for (int i = 0; i < 4; i++) {
        float4 v = __ldcg((const float4*)(s + i*4));
        *(float4*)(d + i*4) = v;
    }
}

// Stage weight tile for 24 gate-cols (8 j x 3 gates) x 64 k, transposed [k][26]
// col c = g*8 + jj -> W row g*HDIM + jbase + jj, row stride HDIM
__device__ __forceinline__ void stage_w24(const float* __restrict__ W, int jbase, int k0,
                                          float* __restrict__ dst) {
    const int tid = threadIdx.x;
    for (int i = tid; i < 24*16; i += 256) {
        int c  = i >> 4;
        int kk = (i & 15) << 2;
        int row = (c >> 3)*HDIM + jbase + (c & 7);
        float4 v = *(const float4*)(W + (size_t)row*HDIM + k0 + kk);
        dst[(kk+0)*26+c] = v.x; dst[(kk+1)*26+c] = v.y;
        dst[(kk+2)*26+c] = v.z; dst[(kk+3)*26+c] = v.w;
    }
}

// GRU2/3 phase: gi = x@wih^T, gh = h@whh^T, pointwise, residual. One block = 8 j.
__device__ void gru23_phase(float* sm,
                            const float* __restrict__ x,
                            const float* __restrict__ wih, const float* __restrict__ bih,
                            const float* __restrict__ hin,
                            const float* __restrict__ whh, const float* __restrict__ bhh,
                            float* __restrict__ hout, float* __restrict__ rout, int jbase)
{
    float* xs = sm;
    float* hs = sm + 64*68;
    float* wi = sm + 2*64*68;
    float* wh = wi + 64*26;

    const int tid  = threadIdx.x;
    const int wid  = tid >> 5, lane = tid & 31;
    const int bg   = lane & 7, cg = lane >> 3;
    const int c0   = cg*6;
    const int kb   = wid << 3;

    float aI[6][8] = {};
    float aH[6][8] = {};

    for (int k0 = 0; k0 < HDIM; k0 += 64) {
        stage_act2(x,   k0, xs);
        stage_act2(hin, k0, hs);
        stage_w24(wih, jbase, k0, wi);
        stage_w24(whh, jbase, k0, wh);
        __syncthreads();
#pragma unroll
        for (int kk = 0; kk < 8; kk++) {
            const int k = kb + kk;
            float xv[8], hv[8];
#pragma unroll
            for (int i = 0; i < 8; i++) {
                xv[i] = xs[(bg + 8*i)*68 + k];
                hv[i] = hs[(bg + 8*i)*68 + k];
            }
            float2 wiA = *(const float2*)&wi[k*26 + c0];
            float2 wiB = *(const float2*)&wi[k*26 + c0 + 2];
            float2 wiC = *(const float2*)&wi[k*26 + c0 + 4];
            float2 whA = *(const float2*)&wh[k*26 + c0];
            float2 whB = *(const float2*)&wh[k*26 + c0 + 2];
            float2 whC = *(const float2*)&wh[k*26 + c0 + 4];
            float wiv[6] = {wiA.x,wiA.y,wiB.x,wiB.y,wiC.x,wiC.y};
            float whv[6] = {whA.x,whA.y,whB.x,whB.y,whC.x,whC.y};
#pragma unroll
            for (int c = 0; c < 6; c++)
#pragma unroll
                for (int i = 0; i < 8; i++) {
                    aI[c][i] = fmaf(xv[i], wiv[c], aI[c][i]);
                    aH[c][i] = fmaf(hv[i], whv[c], aH[c][i]);
                }
        }
        __syncthreads();
    }

    // 4-buffer partial reduction (aliases staging smem; safe after last sync)
    float* myred = sm + (size_t)(wid & 3)*(64*52);
    if (wid < 4) {
#pragma unroll
        for (int c = 0; c < 6; c++)
#pragma unroll
            for (int i = 0; i < 8; i++) {
                myred[(bg+8*i)*52 + c0 + c]      = aI[c][i];
                myred[(bg+8*i)*52 + 24 + c0 + c] = aH[c][i];
            }
    }
    __syncthreads();
    if (wid >= 4) {
#pragma unroll
        for (int c = 0; c < 6; c++)
#pragma unroll
            for (int i = 0; i < 8; i++) {
                myred[(bg+8*i)*52 + c0 + c]      += aI[c][i];
                myred[(bg+8*i)*52 + 24 + c0 + c] += aH[c][i];
            }
    }
    __syncthreads();

    // pointwise GRU + residual
    for (int e = tid; e < 512; e += 256) {
        const int b = e >> 3, jj = e & 7;
        const int j = jbase + jj;
        float gI[3], gH[3];
#pragma unroll
        for (int g = 0; g < 3; g++) {
            int c = g*8 + jj;
            gI[g] = sm[b*52+c] + sm[64*52 + b*52+c] + sm[2*64*52 + b*52+c] + sm[3*64*52 + b*52+c];
            gH[g] = sm[b*52+24+c] + sm[64*52 + b*52+24+c] + sm[2*64*52 + b*52+24+c] + sm[3*64*52 + b*52+24+c];
        }
        float r = sigf(gI[0] + bih[j]        + gH[0] + bhh[j]);
        float z = sigf(gI[1] + bih[HDIM+j]   + gH[1] + bhh[HDIM+j]);
        float n = tanhf(gI[2] + bih[2*HDIM+j] + r*(gH[2] + bhh[2*HDIM+j]));
        float hp = __ldcg(&hin[b*HDIM + j]);
        float h  = (1.f - z)*n + z*hp;
        hout[b*HDIM + j] = h;
        rout[b*HDIM + j] = h + __ldcg(&x[b*HDIM + j]);
    }
}

// GRU1 phase: gi precomputed in gmem (incl bih); only gh GEMM. One block = 8 j.
__device__ void gru1_phase(float* sm,
                           const float* __restrict__ gi,
                           const float* __restrict__ hin,
                           const float* __restrict__ whh, const float* __restrict__ bhh,
                           float* __restrict__ hout, int jbase)
{
    float* hs = sm;
    float* wh = sm + 64*68;

    const int tid  = threadIdx.x;
    const int wid  = tid >> 5, lane = tid & 31;
    const int bg   = lane & 7, cg = lane >> 3;
    const int c0   = cg*6;
    const int kb   = wid << 3;

    float aH[6][8] = {};

    for (int k0 = 0; k0 < HDIM; k0 += 64) {
        stage_act2(hin, k0, hs);
        stage_w24(whh, jbase, k0, wh);
        __syncthreads();
#pragma unroll
        for (int kk = 0; kk < 8; kk++) {
            const int k = kb + kk;
            float hv[8];
#pragma unroll
            for (int i = 0; i < 8; i++) hv[i] = hs[(bg + 8*i)*68 + k];
            float2 whA = *(const float2*)&wh[k*26 + c0];
            float2 whB = *(const float2*)&wh[k*26 + c0 + 2];
            float2 whC = *(const float2*)&wh[k*26 + c0 + 4];
            float whv[6] = {whA.x,whA.y,whB.x,whB.y,whC.x,whC.y};
#pragma unroll
            for (int c = 0; c < 6; c++)
#pragma unroll
                for (int i = 0; i < 8; i++)
                    aH[c][i] = fmaf(hv[i], whv[c], aH[c][i]);
        }
        __syncthreads();
    }

    float* myred = sm + (size_t)(wid & 3)*(64*52);
    if (wid < 4) {
#pragma unroll
        for (int c = 0; c < 6; c++)
#pragma unroll
            for (int i = 0; i < 8; i++)
                myred[(bg+8*i)*52 + c0 + c] = aH[c][i];
    }
    __syncthreads();
    if (wid >= 4) {
#pragma unroll
        for (int c = 0; c < 6; c++)
#pragma unroll
            for (int i = 0; i < 8; i++)
                myred[(bg+8*i)*52 + c0 + c] += aH[c][i];
    }
    __syncthreads();

    for (int e = tid; e < 512; e += 256) {
        const int b = e >> 3, jj = e & 7;
        const int j = jbase + jj;
        float gH[3];
#pragma unroll
        for (int g = 0; g < 3; g++) {
            int c = g*8 + jj;
            gH[g] = sm[b*52+c] + sm[64*52 + b*52+c] + sm[2*64*52 + b*52+c] + sm[3*64*52 + b*52+c];
        }
        const float* gib = gi + (size_t)b*H3;
        float r = sigf(gib[j]          + gH[0] + bhh[j]);
        float z = sigf(gib[HDIM+j]     + gH[1] + bhh[HDIM+j]);
        float n = tanhf(gib[2*HDIM+j]  + r*(gH[2] + bhh[2*HDIM+j]));
        float hp = __ldcg(&hin[b*HDIM + j]);
        hout[b*HDIM + j] = (1.f - z)*n + z*hp;
    }
}

// FC phase (8 cols): dst[b, cbase+c] = x[b,:1024]@W(cbase+c,:1024)^T + add[b, cbase+c]
__device__ void fc8_phase(float* sm,
                          const float* __restrict__ x,
                          const float* __restrict__ W, int wstride,
                          const float* __restrict__ add, int addStride,
                          float* __restrict__ dst, size_t dstStride, int cbase)
{
    float* xs = sm;
    float* ws = sm + 64*68;

    const int tid  = threadIdx.x;
    const int wid  = tid >> 5, lane = tid & 31;
    const int bg   = lane & 7, cg = lane >> 3;
    const int c0   = cg*2;
    const int kb   = wid << 3;

    float acc[2][8] = {};

    for (int k0 = 0; k0 < HDIM; k0 += 64) {
        stage_act2(x, k0, xs);
        if (tid < 128) {
            int c  = tid >> 4;
            int kk = (tid & 15) << 2;
            float4 v = *(const float4*)(W + (size_t)(cbase + c)*wstride + k0 + kk);
            ws[(kk+0)*10+c] = v.x; ws[(kk+1)*10+c] = v.y;
            ws[(kk+2)*10+c] = v.z; ws[(kk+3)*10+c] = v.w;
        }
        __syncthreads();
#pragma unroll
        for (int kk = 0; kk < 8; kk++) {
            const int k = kb + kk;
            float2 w = *(const float2*)&ws[k*10 + c0];
#pragma unroll
            for (int i = 0; i < 8; i++) {
                float xv = xs[(bg + 8*i)*68 + k];
                acc[0][i] = fmaf(xv, w.x, acc[0][i]);
                acc[1][i] = fmaf(xv, w.y, acc[1][i]);
            }
        }
        __syncthreads();
    }

    float* myred = sm + (size_t)(wid & 3)*(64*52);
    if (wid < 4) {
#pragma unroll
        for (int c = 0; c < 2; c++)
#pragma unroll
            for (int i = 0; i < 8; i++)
                myred[(bg+8*i)*52 + c0 + c] = acc[c][i];
    }
    __syncthreads();
    if (wid >= 4) {
#pragma unroll
        for (int c = 0; c < 2; c++)
#pragma unroll
            for (int i = 0; i < 8; i++)
                myred[(bg+8*i)*52 + c0 + c] += acc[c][i];
    }
    __syncthreads();

    for (int e = tid; e < 512; e += 256) {
        const int b = e >> 3, c = e & 7;
        float v = sm[b*52+c] + sm[64*52 + b*52+c] + sm[2*64*52 + b*52+c] + sm[3*64*52 + b*52+c]
                + __ldcg(&add[b*addStride + cbase + c]);
        dst[(size_t)b*dstStride + cbase + c] = v;
    }
}

// ---------------- persistent decode kernel ----------------
__global__ void __launch_bounds__(256,1) decode_persist(
    const float* __restrict__ gi1, const float* __restrict__ dm, const float* __restrict__ om,
    const float* __restrict__ g1_whh, const float* __restrict__ g1_bhh,
    const float* __restrict__ att_w,
    const float* __restrict__ g2_wih, const float* __restrict__ g2_bih,
    const float* __restrict__ g2_whh, const float* __restrict__ g2_bhh,
    const float* __restrict__ g3_wih, const float* __restrict__ g3_bih,
    const float* __restrict__ g3_whh, const float* __restrict__ g3_bhh,
    const float* __restrict__ proj_w,
    float* __restrict__ h1, float* __restrict__ h2, float* __restrict__ h3,
    float* __restrict__ d2, float* __restrict__ r2, float* __restrict__ r3,
    float* __restrict__ out)
{
    extern __shared__ float sm[];
    const int blk = blockIdx.x;
    unsigned gen = *(volatile unsigned*)&g_gen;

    for (int t = 0; t < TDEC; t++) {
        const int pi = t & 1, po = pi ^ 1;
        // S1: blocks 0-127 -> GRU1(t); blocks 128-147 -> output projection for t-1
        if (blk < 128) {
            gru1_phase(sm, gi1 + (size_t)t*BB*H3,
                       h1 + (size_t)pi*BB*HDIM, g1_whh, g1_bhh,
                       h1 + (size_t)po*BB*HDIM, blk*8);
        } else if (t > 0) {
            fc8_phase(sm, r3, proj_w, HDIM+EDIM,
                      om + (size_t)(t-1)*BB*OUTC, OUTC,
                      out + (size_t)(t-1)*OUTC, (size_t)TDEC*OUTC, (blk-128)*8);
        }
        gridsync(gen);
        // S2: d2 = h1 @ att_w[:, :1024]^T + dm[t]
        if (blk < 128) {
            fc8_phase(sm, h1 + (size_t)po*BB*HDIM, att_w, HDIM+EDIM,
                      dm + (size_t)t*BB*HDIM, HDIM,
                      d2, HDIM, blk*8);
        }
        gridsync(gen);
        // S3: GRU2 + residual r2 = h2 + d2
        if (blk < 128) {
            gru23_phase(sm, d2, g2_wih, g2_bih,
                        h2 + (size_t)pi*BB*HDIM, g2_whh, g2_bhh,
                        h2 + (size_t)po*BB*HDIM, r2, blk*8);
        }
        gridsync(gen);
        // S4: GRU3 + residual r3 = h3 + r2
        if (blk < 128) {
            gru23_phase(sm, r2, g3_wih, g3_bih,
                        h3 + (size_t)pi*BB*HDIM, g3_whh, g3_bhh,
                        h3 + (size_t)po*BB*HDIM, r3, blk*8);
        }
        gridsync(gen);
    }
    // final output projection for t = TDEC-1 (no barrier needed; kernel end syncs)
    if (blk >= 128) {
        fc8_phase(sm, r3, proj_w, HDIM+EDIM,
                  om + (size_t)(TDEC-1)*BB*OUTC, OUTC,
                  out + (size_t)(TDEC-1)*OUTC, (size_t)TDEC*OUTC, (blk-128)*8);
    }
}

// ---------------- host ----------------
extern "C" void kernel_launch(void* const* d_in, const int* in_sizes, int n_in,
                              void* d_out, int out_size) {
    const float* memorys = (const float*)d_in[0];
    const float* dec_in  = (const float*)d_in[1];
    // d_in[2] = memory_lengths (unused by reference decode)
    const float* pre_w1 = (const float*)d_in[3];
    const float* pre_b1 = (const float*)d_in[4];
    const float* pre_w2 = (const float*)d_in[5];
    const float* pre_b2 = (const float*)d_in[6];
    const float* g1_wih = (const float*)d_in[7];
    const float* g1_whh = (const float*)d_in[8];
    const float* g1_bih = (const float*)d_in[9];
    const float* g1_bhh = (const float*)d_in[10];
    const float* att_w  = (const float*)d_in[11];
    const float* att_b  = (const float*)d_in[12];
    const float* g2_wih = (const float*)d_in[13];
    const float* g2_whh = (const float*)d_in[14];
    const float* g2_bih = (const float*)d_in[15];
    const float* g2_bhh = (const float*)d_in[16];
    const float* g3_wih = (const float*)d_in[17];
    const float* g3_whh = (const float*)d_in[18];
    const float* g3_bih = (const float*)d_in[19];
    const float* g3_bhh = (const float*)d_in[20];
    const float* proj_w = (const float*)d_in[21];
    const float* proj_b = (const float*)d_in[22];
    float* out = (float*)d_out;

    float *di, *x1, *x2, *memp, *gi1, *dm, *om, *h1, *h2, *h3, *d2, *r2, *r3;
    cudaGetSymbolAddress((void**)&di,   g_di);
    cudaGetSymbolAddress((void**)&x1,   g_x1);
    cudaGetSymbolAddress((void**)&x2,   g_x2);
    cudaGetSymbolAddress((void**)&memp, g_mem);
    cudaGetSymbolAddress((void**)&gi1,  g_gi1);
    cudaGetSymbolAddress((void**)&dm,   g_dm);
    cudaGetSymbolAddress((void**)&om,   g_om);
    cudaGetSymbolAddress((void**)&h1,   g_h1);
    cudaGetSymbolAddress((void**)&h2,   g_h2);
    cudaGetSymbolAddress((void**)&h3,   g_h3);
    cudaGetSymbolAddress((void**)&d2,   g_d2);
    cudaGetSymbolAddress((void**)&r2,   g_r2);
    cudaGetSymbolAddress((void**)&r3,   g_r3);

    // ---- time-parallel precompute ----
    build_di<<<(ROWS*MDIM + 255)/256, 256>>>(dec_in, di);
    pool_mem<<<(ROWS*EDIM + 255)/256, 256>>>(memorys, memp);
    fc128<<<dim3(2, 500), 256>>>(di, MDIM, nullptr, 0, pre_w1, MDIM, 0, pre_b1, x1, PDIM, 1);
    fc128<<<dim3(2, 500), 256>>>(x1, PDIM, nullptr, 0, pre_w2, PDIM, 0, pre_b2, x2, PDIM, 1);
    fc128<<<dim3(24, 500), 256>>>(x2, PDIM, memp, EDIM, g1_wih, PDIM+EDIM, 0, g1_bih, gi1, H3, 0);
    fc128<<<dim3(8, 500), 256>>>(memp, EDIM, nullptr, 0, att_w, HDIM+EDIM, HDIM, att_b, dm, HDIM, 0);
    fc128<<<dim3(2, 500), 256>>>(memp, EDIM, nullptr, 0, proj_w, HDIM+EDIM, HDIM, proj_b, om, OUTC, 0);

    cudaMemsetAsync(h1, 0, sizeof(float)*2*BB*HDIM, 0);
    cudaMemsetAsync(h2, 0, sizeof(float)*2*BB*HDIM, 0);
    cudaMemsetAsync(h3, 0, sizeof(float)*2*BB*HDIM, 0);

    // ---- persistent sequential decode (single launch, grid-wide barriers) ----
    cudaFuncSetAttribute(decode_persist, cudaFuncAttributeMaxDynamicSharedMemorySize, SMEM_BYTES);
    decode_persist<<<NBLK, 256, SMEM_BYTES>>>(
        gi1, dm, om,
        g1_whh, g1_bhh, att_w,
        g2_wih, g2_bih, g2_whh, g2_bhh,
        g3_wih, g3_bih, g3_whh, g3_bhh,
        proj_w,
        h1, h2, h3, d2, r2, r3, out);
}

// round 16
// speedup vs baseline: 1.1654x; 1.1654x over previous
#include <cuda_runtime.h>
#include <math.h>
#include <stdint.h>
#include <stddef.h>

// Problem constants
#define BB    64
#define TDEC  1000
#define TMEL  2000
#define MDIM  80
#define PDIM  256
#define EDIM  512
#define HDIM  1024
#define H3    3072
#define OUTC  160
#define ROWS  (TDEC*BB)   // 64000

#define NBLK  148

// Dynamic smem layout (floats) for the persistent kernel
#define XS0 0
#define XS1 4352
#define HS0 8704
#define HS1 13056
#define WI0 17408
#define WI1 19072
#define WH0 20736
#define WH1 22400
#define SMEM_FLOATS 24064
#define SMEM_BYTES  (SMEM_FLOATS*4)   // 96256 bytes

typedef unsigned long long ull;

// ---------------- scratch (static device memory; no allocations) ----------------
__device__ float g_di [ROWS*MDIM];
__device__ float g_x1 [ROWS*PDIM];
__device__ float g_x2 [ROWS*PDIM];
__device__ float g_mem[ROWS*EDIM];
__device__ float g_gi1[(size_t)ROWS*H3];
__device__ float g_dm [ROWS*HDIM];
__device__ float g_om [ROWS*OUTC];
__device__ float g_h1 [2*BB*HDIM];
__device__ float g_h2 [2*BB*HDIM];
__device__ float g_h3 [2*BB*HDIM];
__device__ float g_d2 [BB*HDIM];
__device__ float g_r2 [BB*HDIM];
__device__ float g_r3 [BB*HDIM];

__device__ unsigned g_count = 0;
__device__ unsigned g_gen   = 0;

__device__ __forceinline__ float sigf(float x) { return 1.f/(1.f+expf(-x)); }

// packed f32x2 helpers (FFMA2 — only reachable via PTX)
__device__ __forceinline__ ull pack2(float a, float b) {
    ull r; asm("mov.b64 %0, {%1, %2};" : "=l"(r) : "f"(a), "f"(b)); return r;
}
__device__ __forceinline__ void fma2(ull& d, ull a, ull b) {
    asm("fma.rn.f32x2 %0, %1, %2, %0;" : "+l"(d) : "l"(a), "l"(b));
}
__device__ __forceinline__ float2 unpack2(ull v) {
    float lo, hi; asm("mov.b64 {%0, %1}, %2;" : "=f"(lo), "=f"(hi) : "l"(v));
    float2 f; f.x = lo; f.y = hi; return f;
}

// ---------------- grid barrier (all NBLK blocks resident) ----------------
__device__ __forceinline__ void gridsync(unsigned &gen) {
    __threadfence();
    __syncthreads();
    if (threadIdx.x == 0) {
        unsigned target = gen + 1u;
        if (atomicAdd(&g_count, 1u) == NBLK - 1u) {
            g_count = 0;
            __threadfence();
            atomicExch(&g_gen, target);
        } else {
            while (*(volatile unsigned*)&g_gen != target) { }
        }
    }
    __syncthreads();
    gen += 1u;
}

// ---------------- elementwise precompute ----------------
__global__ void build_di(const float* __restrict__ dec, float* __restrict__ di) {
    int i = blockIdx.x*blockDim.x + threadIdx.x;
    if (i >= ROWS*MDIM) return;
    int m = i % MDIM;
    int r = i / MDIM;
    int b = r % BB;
    int t = r / BB;
    di[i] = (t == 0) ? 0.f : dec[((size_t)b*TMEL + (2*t-1))*MDIM + m];
}

__global__ void pool_mem(const float* __restrict__ mems, float* __restrict__ mem) {
    int i = blockIdx.x*blockDim.x + threadIdx.x;
    if (i >= ROWS*EDIM) return;
    int e = i % EDIM;
    int r = i / EDIM;
    int b = r % BB;
    int t = r / BB;
    size_t base = ((size_t)b*TMEL + 2*t)*EDIM + e;
    mem[i] = 0.5f*(mems[base] + mems[base + EDIM]);
}

// ---------------- big parallel SGEMM (precompute; validated) ----------------
__global__ void __launch_bounds__(256) fc128(
    const float* __restrict__ A1, int K1,
    const float* __restrict__ A2, int K2,
    const float* __restrict__ W, int wstride, int woff,
    const float* __restrict__ bias,
    float* __restrict__ C, int N, int doRelu)
{
    __shared__ float As[8][128];
    __shared__ float Ws[8][128];
    const int tid = threadIdx.x;
    const int rowBase = blockIdx.y << 7;
    const int colBase = blockIdx.x << 7;
    const int tx = tid & 15;
    const int ty = tid >> 4;
    const int la_row = tid >> 1;
    const int la_k   = (tid & 1) << 2;
    const int K = K1 + K2;
    float acc[8][8] = {};
    for (int k0 = 0; k0 < K; k0 += 8) {
        {
            int r = rowBase + la_row;
            int k = k0 + la_k;
            const float* src; int kk;
            if (k < K1) { src = A1 + (size_t)r*K1; kk = k; }
            else        { src = A2 + (size_t)r*K2; kk = k - K1; }
            float4 v = *(const float4*)(src + kk);
            As[la_k+0][la_row] = v.x; As[la_k+1][la_row] = v.y;
            As[la_k+2][la_row] = v.z; As[la_k+3][la_row] = v.w;
        }
        {
            int c = colBase + la_row;
            float4 v = make_float4(0.f,0.f,0.f,0.f);
            if (c < N) v = *(const float4*)(W + (size_t)c*wstride + woff + k0 + la_k);
            Ws[la_k+0][la_row] = v.x; Ws[la_k+1][la_row] = v.y;
            Ws[la_k+2][la_row] = v.z; Ws[la_k+3][la_row] = v.w;
        }
        __syncthreads();
#pragma unroll
        for (int kk = 0; kk < 8; kk++) {
            float4 a0 = *(const float4*)&As[kk][ty<<3];
            float4 a1 = *(const float4*)&As[kk][(ty<<3)+4];
            float4 b0 = *(const float4*)&Ws[kk][tx<<3];
            float4 b1 = *(const float4*)&Ws[kk][(tx<<3)+4];
            float a[8]  = {a0.x,a0.y,a0.z,a0.w,a1.x,a1.y,a1.z,a1.w};
            float bw[8] = {b0.x,b0.y,b0.z,b0.w,b1.x,b1.y,b1.z,b1.w};
#pragma unroll
            for (int i = 0; i < 8; i++)
#pragma unroll
                for (int j = 0; j < 8; j++)
                    acc[i][j] = fmaf(a[i], bw[j], acc[i][j]);
        }
        __syncthreads();
    }
#pragma unroll
    for (int i = 0; i < 8; i++) {
        int r = rowBase + (ty<<3) + i;
#pragma unroll
        for (int j = 0; j < 8; j++) {
            int c = colBase + (tx<<3) + j;
            if (c < N) {
                float v = acc[i][j] + bias[c];
                if (doRelu) v = fmaxf(v, 0.f);
                C[(size_t)r*N + c] = v;
            }
        }
    }
}

// ---------------- staging helpers (persistent kernel) ----------------
struct AP { float4 v[4]; };   // one activation chunk slice per thread (16 floats)
__device__ __forceinline__ void act_ld(const float* __restrict__ src, int k0, AP& p) {
    const int tid = threadIdx.x;
    const int b  = tid >> 2;
    const int kq = (tid & 3) << 4;
    const float* s = src + b*HDIM + k0 + kq;
#pragma unroll
    for (int i = 0; i < 4; i++) p.v[i] = __ldcg((const float4*)(s + 4*i));
}
__device__ __forceinline__ void act_st(float* __restrict__ dst, const AP& p) {
    const int tid = threadIdx.x;
    const int b  = tid >> 2;
    const int kq = (tid & 3) << 4;
    float* d = dst + b*68 + kq;
#pragma unroll
    for (int i = 0; i < 4; i++) *(float4*)(d + 4*i) = p.v[i];
}

struct WP { float4 v[2]; };   // 24-col weight tile slice per thread
__device__ __forceinline__ void w_ld(const float* __restrict__ W, int jbase, int k0, WP& p) {
    const int tid = threadIdx.x;
#pragma unroll
    for (int r = 0; r < 2; r++) {
        int i = tid + (r << 8);
        if (i < 384) {
            int c  = i >> 4, kk = (i & 15) << 2;
            int row = (c >> 3)*HDIM + jbase + (c & 7);
            p.v[r] = *(const float4*)(W + (size_t)row*HDIM + k0 + kk);
        }
    }
}
__device__ __forceinline__ void w_st(float* __restrict__ dst, const WP& p) {
    const int tid = threadIdx.x;
#pragma unroll
    for (int r = 0; r < 2; r++) {
        int i = tid + (r << 8);
        if (i < 384) {
            int c  = i >> 4, kk = (i & 15) << 2;
            dst[(kk+0)*26+c] = p.v[r].x; dst[(kk+1)*26+c] = p.v[r].y;
            dst[(kk+2)*26+c] = p.v[r].z; dst[(kk+3)*26+c] = p.v[r].w;
        }
    }
}

// legacy combined stagers (for fc8)
__device__ __forceinline__ void stage_act2(const float* __restrict__ src, int k0,
                                           float* __restrict__ dst) {
    const int tid = threadIdx.x;
    const int b  = tid >> 2;
    const int kq = (tid & 3) << 4;
    const float* s = src + b*HDIM + k0 + kq;
    float* d = dst + b*68 + kq;
#pragma unroll
    for (int i = 0; i < 4; i++) {
        float4 v = __ldcg((const float4*)(s + i*4));
        *(float4*)(d + i*4) = v;
    }
}

// ---------------- GRU2/3 phase (dual-GEMM, packed FMA, double-buffered) ----------------
__device__ void gru23_phase(float* sm,
                            const float* __restrict__ x,
                            const float* __restrict__ wih, const float* __restrict__ bih,
                            const float* __restrict__ hin,
                            const float* __restrict__ whh, const float* __restrict__ bhh,
                            float* __restrict__ hout, float* __restrict__ rout, int jbase)
{
    const int tid  = threadIdx.x;
    const int wid  = tid >> 5, lane = tid & 31;
    const int bg   = lane & 7, cg = lane >> 3;
    const int c0   = cg*6;
    const bool doI = (wid < 4);
    const int kbase = (wid & 3) << 4;    // 16-k slice per warp within each 64-chunk

    float* xs[2] = { sm+XS0, sm+XS1 };
    float* hs[2] = { sm+HS0, sm+HS1 };
    float* wi[2] = { sm+WI0, sm+WI1 };
    float* wh[2] = { sm+WH0, sm+WH1 };

    ull acc[3][8] = {};

    AP pa, ph; WP pwi, pwh;
    act_ld(x, 0, pa);   act_ld(hin, 0, ph);
    w_ld(wih, jbase, 0, pwi);  w_ld(whh, jbase, 0, pwh);
    act_st(xs[0], pa);  act_st(hs[0], ph);
    w_st(wi[0], pwi);   w_st(wh[0], pwh);
    __syncthreads();

    for (int c = 0; c < 16; c++) {
        const int cur = c & 1, nxt = cur ^ 1;
        if (c < 15) {
            const int k0 = (c+1) << 6;
            act_ld(x, k0, pa);   act_ld(hin, k0, ph);
            w_ld(wih, jbase, k0, pwi);  w_ld(whh, jbase, k0, pwh);
        }
        const float* as = doI ? xs[cur] : hs[cur];
        const float* ws = doI ? wi[cur] : wh[cur];
#pragma unroll
        for (int kk = 0; kk < 16; kk++) {
            const int k = kbase + kk;
            ull xd[8];
#pragma unroll
            for (int i = 0; i < 8; i++) {
                float v = as[(bg + 8*i)*68 + k];
                xd[i] = pack2(v, v);
            }
#pragma unroll
            for (int p = 0; p < 3; p++) {
                float2 wv = *(const float2*)&ws[k*26 + c0 + 2*p];
                ull wd = pack2(wv.x, wv.y);
#pragma unroll
                for (int i = 0; i < 8; i++) fma2(acc[p][i], xd[i], wd);
            }
        }
        if (c < 15) {
            act_st(xs[nxt], pa);  act_st(hs[nxt], ph);
            w_st(wi[nxt], pwi);   w_st(wh[nxt], pwh);
        }
        __syncthreads();
    }

    // K-split reduction: red[8][64][26]; warps 0-3 = input gates, 4-7 = hidden gates
    float* red = sm;
    float* my = red + wid*(64*26);
#pragma unroll
    for (int p = 0; p < 3; p++)
#pragma unroll
        for (int i = 0; i < 8; i++) {
            float2 v = unpack2(acc[p][i]);
            *(float2*)&my[(bg + 8*i)*26 + c0 + 2*p] = v;
        }
    __syncthreads();

    for (int e = tid; e < 512; e += 256) {
        const int b = e >> 3, jj = e & 7;
        const int j = jbase + jj;
        float gI[3], gH[3];
#pragma unroll
        for (int g = 0; g < 3; g++) {
            int cc = g*8 + jj;
            gI[g] = red[0*1664 + b*26+cc] + red[1*1664 + b*26+cc]
                  + red[2*1664 + b*26+cc] + red[3*1664 + b*26+cc];
            gH[g] = red[4*1664 + b*26+cc] + red[5*1664 + b*26+cc]
                  + red[6*1664 + b*26+cc] + red[7*1664 + b*26+cc];
        }
        float r = sigf(gI[0] + bih[j]         + gH[0] + bhh[j]);
        float z = sigf(gI[1] + bih[HDIM+j]    + gH[1] + bhh[HDIM+j]);
        float n = tanhf(gI[2] + bih[2*HDIM+j] + r*(gH[2] + bhh[2*HDIM+j]));
        float hp = __ldcg(&hin[b*HDIM + j]);
        float h  = (1.f - z)*n + z*hp;
        hout[b*HDIM + j] = h;
        rout[b*HDIM + j] = h + __ldcg(&x[b*HDIM + j]);
    }
}

// ---------------- GRU1 phase (hidden GEMM only; gi precomputed) ----------------
__device__ void gru1_phase(float* sm,
                           const float* __restrict__ gi,
                           const float* __restrict__ hin,
                           const float* __restrict__ whh, const float* __restrict__ bhh,
                           float* __restrict__ hout, int jbase)
{
    const int tid  = threadIdx.x;
    const int wid  = tid >> 5, lane = tid & 31;
    const int bg   = lane & 7, cg = lane >> 3;
    const int c0   = cg*6;
    const int kbase = wid << 3;          // 8-k slice per warp (8-way K-split)

    float* hs[2] = { sm+HS0, sm+HS1 };
    float* wh[2] = { sm+WH0, sm+WH1 };

    ull acc[3][8] = {};

    AP ph; WP pwh;
    act_ld(hin, 0, ph);
    w_ld(whh, jbase, 0, pwh);
    act_st(hs[0], ph);
    w_st(wh[0], pwh);
    __syncthreads();

    for (int c = 0; c < 16; c++) {
        const int cur = c & 1, nxt = cur ^ 1;
        if (c < 15) {
            const int k0 = (c+1) << 6;
            act_ld(hin, k0, ph);
            w_ld(whh, jbase, k0, pwh);
        }
        const float* as = hs[cur];
        const float* ws = wh[cur];
#pragma unroll
        for (int kk = 0; kk < 8; kk++) {
            const int k = kbase + kk;
            ull xd[8];
#pragma unroll
            for (int i = 0; i < 8; i++) {
                float v = as[(bg + 8*i)*68 + k];
                xd[i] = pack2(v, v);
            }
#pragma unroll
            for (int p = 0; p < 3; p++) {
                float2 wv = *(const float2*)&ws[k*26 + c0 + 2*p];
                ull wd = pack2(wv.x, wv.y);
#pragma unroll
                for (int i = 0; i < 8; i++) fma2(acc[p][i], xd[i], wd);
            }
        }
        if (c < 15) {
            act_st(hs[nxt], ph);
            w_st(wh[nxt], pwh);
        }
        __syncthreads();
    }

    float* red = sm;
    float* my = red + wid*(64*26);
#pragma unroll
    for (int p = 0; p < 3; p++)
#pragma unroll
        for (int i = 0; i < 8; i++) {
            float2 v = unpack2(acc[p][i]);
            *(float2*)&my[(bg + 8*i)*26 + c0 + 2*p] = v;
        }
    __syncthreads();

    for (int e = tid; e < 512; e += 256) {
        const int b = e >> 3, jj = e & 7;
        const int j = jbase + jj;
        float gH[3];
#pragma unroll
        for (int g = 0; g < 3; g++) {
            int cc = g*8 + jj;
            float s = 0.f;
#pragma unroll
            for (int w = 0; w < 8; w++) s += red[w*1664 + b*26 + cc];
            gH[g] = s;
        }
        const float* gib = gi + (size_t)b*H3;
        float r = sigf(gib[j]           + gH[0] + bhh[j]);
        float z = sigf(gib[HDIM+j]      + gH[1] + bhh[HDIM+j]);
        float n = tanhf(gib[2*HDIM+j]   + r*(gH[2] + bhh[2*HDIM+j]));
        float hp = __ldcg(&hin[b*HDIM + j]);
        hout[b*HDIM + j] = (1.f - z)*n + z*hp;
    }
}

// ---------------- small FC phase (8 cols) ----------------
__device__ void fc8_phase(float* sm,
                          const float* __restrict__ x,
                          const float* __restrict__ W, int wstride,
                          const float* __restrict__ add, int addStride,
                          float* __restrict__ dst, size_t dstStride, int cbase)
{
    float* xs = sm;
    float* ws = sm + 64*68;

    const int tid  = threadIdx.x;
    const int wid  = tid >> 5, lane = tid & 31;
    const int bg   = lane & 7, cg = lane >> 3;
    const int c0   = cg*2;
    const int kb   = wid << 3;

    float acc[2][8] = {};

    for (int k0 = 0; k0 < HDIM; k0 += 64) {
        stage_act2(x, k0, xs);
        if (tid < 128) {
            int c  = tid >> 4;
            int kk = (tid & 15) << 2;
            float4 v = *(const float4*)(W + (size_t)(cbase + c)*wstride + k0 + kk);
            ws[(kk+0)*10+c] = v.x; ws[(kk+1)*10+c] = v.y;
            ws[(kk+2)*10+c] = v.z; ws[(kk+3)*10+c] = v.w;
        }
        __syncthreads();
#pragma unroll
        for (int kk = 0; kk < 8; kk++) {
            const int k = kb + kk;
            float2 w = *(const float2*)&ws[k*10 + c0];
#pragma unroll
            for (int i = 0; i < 8; i++) {
                float xv = xs[(bg + 8*i)*68 + k];
                acc[0][i] = fmaf(xv, w.x, acc[0][i]);
                acc[1][i] = fmaf(xv, w.y, acc[1][i]);
            }
        }
        __syncthreads();
    }

    float* myred = sm + (size_t)(wid & 3)*(64*52);
    if (wid < 4) {
#pragma unroll
        for (int c = 0; c < 2; c++)
#pragma unroll
            for (int i = 0; i < 8; i++)
                myred[(bg+8*i)*52 + c0 + c] = acc[c][i];
    }
    __syncthreads();
    if (wid >= 4) {
#pragma unroll
        for (int c = 0; c < 2; c++)
#pragma unroll
            for (int i = 0; i < 8; i++)
                myred[(bg+8*i)*52 + c0 + c] += acc[c][i];
    }
    __syncthreads();

    for (int e = tid; e < 512; e += 256) {
        const int b = e >> 3, c = e & 7;
        float v = sm[b*52+c] + sm[64*52 + b*52+c] + sm[2*64*52 + b*52+c] + sm[3*64*52 + b*52+c]
                + __ldcg(&add[b*addStride + cbase + c]);
        dst[(size_t)b*dstStride + cbase + c] = v;
    }
}

// ---------------- persistent decode kernel ----------------
__global__ void __launch_bounds__(256,1) decode_persist(
    const float* __restrict__ gi1, const float* __restrict__ dm, const float* __restrict__ om,
    const float* __restrict__ g1_whh, const float* __restrict__ g1_bhh,
    const float* __restrict__ att_w,
    const float* __restrict__ g2_wih, const float* __restrict__ g2_bih,
    const float* __restrict__ g2_whh, const float* __restrict__ g2_bhh,
    const float* __restrict__ g3_wih, const float* __restrict__ g3_bih,
    const float* __restrict__ g3_whh, const float* __restrict__ g3_bhh,
    const float* __restrict__ proj_w,
    float* __restrict__ h1, float* __restrict__ h2, float* __restrict__ h3,
    float* __restrict__ d2, float* __restrict__ r2, float* __restrict__ r3,
    float* __restrict__ out)
{
    extern __shared__ float sm[];
    const int blk = blockIdx.x;
    unsigned gen = *(volatile unsigned*)&g_gen;

    for (int t = 0; t < TDEC; t++) {
        const int pi = t & 1, po = pi ^ 1;
        // S1: blocks 0-127 -> GRU1(t); blocks 128-147 -> output projection for t-1
        if (blk < 128) {
            gru1_phase(sm, gi1 + (size_t)t*BB*H3,
                       h1 + (size_t)pi*BB*HDIM, g1_whh, g1_bhh,
                       h1 + (size_t)po*BB*HDIM, blk*8);
        } else if (t > 0) {
            fc8_phase(sm, r3, proj_w, HDIM+EDIM,
                      om + (size_t)(t-1)*BB*OUTC, OUTC,
                      out + (size_t)(t-1)*OUTC, (size_t)TDEC*OUTC, (blk-128)*8);
        }
        gridsync(gen);
        // S2: d2 = h1 @ att_w[:, :1024]^T + dm[t]
        if (blk < 128) {
            fc8_phase(sm, h1 + (size_t)po*BB*HDIM, att_w, HDIM+EDIM,
                      dm + (size_t)t*BB*HDIM, HDIM,
                      d2, HDIM, blk*8);
        }
        gridsync(gen);
        // S3: GRU2 + residual r2 = h2 + d2
        if (blk < 128) {
            gru23_phase(sm, d2, g2_wih, g2_bih,
                        h2 + (size_t)pi*BB*HDIM, g2_whh, g2_bhh,
                        h2 + (size_t)po*BB*HDIM, r2, blk*8);
        }
        gridsync(gen);
        // S4: GRU3 + residual r3 = h3 + r2
        if (blk < 128) {
            gru23_phase(sm, r2, g3_wih, g3_bih,
                        h3 + (size_t)pi*BB*HDIM, g3_whh, g3_bhh,
                        h3 + (size_t)po*BB*HDIM, r3, blk*8);
        }
        gridsync(gen);
    }
    // final output projection for t = TDEC-1
    if (blk >= 128) {
        fc8_phase(sm, r3, proj_w, HDIM+EDIM,
                  om + (size_t)(TDEC-1)*BB*OUTC, OUTC,
                  out + (size_t)(TDEC-1)*OUTC, (size_t)TDEC*OUTC, (blk-128)*8);
    }
}

// ---------------- host ----------------
extern "C" void kernel_launch(void* const* d_in, const int* in_sizes, int n_in,
                              void* d_out, int out_size) {
    const float* memorys = (const float*)d_in[0];
    const float* dec_in  = (const float*)d_in[1];
    // d_in[2] = memory_lengths (unused by reference decode)
    const float* pre_w1 = (const float*)d_in[3];
    const float* pre_b1 = (const float*)d_in[4];
    const float* pre_w2 = (const float*)d_in[5];
    const float* pre_b2 = (const float*)d_in[6];
    const float* g1_wih = (const float*)d_in[7];
    const float* g1_whh = (const float*)d_in[8];
    const float* g1_bih = (const float*)d_in[9];
    const float* g1_bhh = (const float*)d_in[10];
    const float* att_w  = (const float*)d_in[11];
    const float* att_b  = (const float*)d_in[12];
    const float* g2_wih = (const float*)d_in[13];
    const float* g2_whh = (const float*)d_in[14];
    const float* g2_bih = (const float*)d_in[15];
    const float* g2_bhh = (const float*)d_in[16];
    const float* g3_wih = (const float*)d_in[17];
    const float* g3_whh = (const float*)d_in[18];
    const float* g3_bih = (const float*)d_in[19];
    const float* g3_bhh = (const float*)d_in[20];
    const float* proj_w = (const float*)d_in[21];
    const float* proj_b = (const float*)d_in[22];
    float* out = (float*)d_out;

    float *di, *x1, *x2, *memp, *gi1, *dm, *om, *h1, *h2, *h3, *d2, *r2, *r3;
    cudaGetSymbolAddress((void**)&di,   g_di);
    cudaGetSymbolAddress((void**)&x1,   g_x1);
    cudaGetSymbolAddress((void**)&x2,   g_x2);
    cudaGetSymbolAddress((void**)&memp, g_mem);
    cudaGetSymbolAddress((void**)&gi1,  g_gi1);
    cudaGetSymbolAddress((void**)&dm,   g_dm);
    cudaGetSymbolAddress((void**)&om,   g_om);
    cudaGetSymbolAddress((void**)&h1,   g_h1);
    cudaGetSymbolAddress((void**)&h2,   g_h2);
    cudaGetSymbolAddress((void**)&h3,   g_h3);
    cudaGetSymbolAddress((void**)&d2,   g_d2);
    cudaGetSymbolAddress((void**)&r2,   g_r2);
    cudaGetSymbolAddress((void**)&r3,   g_r3);

    // ---- time-parallel precompute ----
    build_di<<<(ROWS*MDIM + 255)/256, 256>>>(dec_in, di);
    pool_mem<<<(ROWS*EDIM + 255)/256, 256>>>(memorys, memp);
    fc128<<<dim3(2, 500), 256>>>(di, MDIM, nullptr, 0, pre_w1, MDIM, 0, pre_b1, x1, PDIM, 1);
    fc128<<<dim3(2, 500), 256>>>(x1, PDIM, nullptr, 0, pre_w2, PDIM, 0, pre_b2, x2, PDIM, 1);
    fc128<<<dim3(24, 500), 256>>>(x2, PDIM, memp, EDIM, g1_wih, PDIM+EDIM, 0, g1_bih, gi1, H3, 0);
    fc128<<<dim3(8, 500), 256>>>(memp, EDIM, nullptr, 0, att_w, HDIM+EDIM, HDIM, att_b, dm, HDIM, 0);
    fc128<<<dim3(2, 500), 256>>>(memp, EDIM, nullptr, 0, proj_w, HDIM+EDIM, HDIM, proj_b, om, OUTC, 0);

    cudaMemsetAsync(h1, 0, sizeof(float)*2*BB*HDIM, 0);
    cudaMemsetAsync(h2, 0, sizeof(float)*2*BB*HDIM, 0);
    cudaMemsetAsync(h3, 0, sizeof(float)*2*BB*HDIM, 0);

    // ---- persistent sequential decode ----
    cudaFuncSetAttribute(decode_persist, cudaFuncAttributeMaxDynamicSharedMemorySize, SMEM_BYTES);
    decode_persist<<<NBLK, 256, SMEM_BYTES>>>(
        gi1, dm, om,
        g1_whh, g1_bhh, att_w,
        g2_wih, g2_bih, g2_whh, g2_bhh,
        g3_wih, g3_bih, g3_whh, g3_bhh,
        proj_w,
        h1, h2, h3, d2, r2, r3, out);
}